// round 4
// baseline (speedup 1.0000x reference)
#include <cuda_runtime.h>
#include <math.h>

#define T_SEQ 4096
#define C_MODEL 1024
#define NHEADS 16
#define DHEAD 64

// Scratch (allocation-free rule: __device__ globals)
__device__ float g_q[T_SEQ * C_MODEL];
__device__ float g_k[T_SEQ * C_MODEL];
__device__ float g_v[T_SEQ * C_MODEL];
__device__ float g_attn[T_SEQ * C_MODEL];

// ---------------------------------------------------------------------------
// C[M,N] = A[M,K] @ B[N,K]^T + bias[N]
// 128x128 tile, BK=8, 256 threads, 8x8 microtile per thread.
// ---------------------------------------------------------------------------
#define GPITCH 132

__global__ __launch_bounds__(256) void gemm_bias(
    const float* __restrict__ A, const float* __restrict__ B,
    const float* __restrict__ bias, float* __restrict__ Cout,
    int M, int N, int K) {
  __shared__ float As[8][GPITCH];
  __shared__ float Bs[8][GPITCH];
  const int tid = threadIdx.x;
  const int ty = tid >> 4;
  const int tx = tid & 15;
  const int bm = blockIdx.y * 128;
  const int bn = blockIdx.x * 128;
  const int lrow = tid >> 1;
  const int lcol = (tid & 1) << 2;

  float acc[8][8];
#pragma unroll
  for (int i = 0; i < 8; i++)
#pragma unroll
    for (int j = 0; j < 8; j++) acc[i][j] = 0.f;

  const float* Aptr = A + (bm + lrow) * K + lcol;
  const float* Bptr = B + (bn + lrow) * K + lcol;

  for (int k0 = 0; k0 < K; k0 += 8) {
    float4 a4 = *(const float4*)(Aptr + k0);
    float4 b4 = *(const float4*)(Bptr + k0);
    __syncthreads();
    As[lcol + 0][lrow] = a4.x; As[lcol + 1][lrow] = a4.y;
    As[lcol + 2][lrow] = a4.z; As[lcol + 3][lrow] = a4.w;
    Bs[lcol + 0][lrow] = b4.x; Bs[lcol + 1][lrow] = b4.y;
    Bs[lcol + 2][lrow] = b4.z; Bs[lcol + 3][lrow] = b4.w;
    __syncthreads();
#pragma unroll
    for (int k = 0; k < 8; k++) {
      float a[8], b[8];
      *(float4*)&a[0] = *(const float4*)&As[k][ty * 8 + 0];
      *(float4*)&a[4] = *(const float4*)&As[k][ty * 8 + 4];
      *(float4*)&b[0] = *(const float4*)&Bs[k][tx * 8 + 0];
      *(float4*)&b[4] = *(const float4*)&Bs[k][tx * 8 + 4];
#pragma unroll
      for (int i = 0; i < 8; i++)
#pragma unroll
        for (int j = 0; j < 8; j++) acc[i][j] = fmaf(a[i], b[j], acc[i][j]);
    }
  }

#pragma unroll
  for (int i = 0; i < 8; i++) {
    const int r = bm + ty * 8 + i;
#pragma unroll
    for (int j = 0; j < 8; j += 4) {
      const int c = bn + tx * 8 + j;
      float4 o;
      o.x = acc[i][j + 0] + bias[c + 0];
      o.y = acc[i][j + 1] + bias[c + 1];
      o.z = acc[i][j + 2] + bias[c + 2];
      o.w = acc[i][j + 3] + bias[c + 3];
      *(float4*)(Cout + r * N + c) = o;
    }
  }
}

// ---------------------------------------------------------------------------
// Causal flash attention, fp32, gemm-style tiling.
// One block per (head, 128-row q block). 256 threads.
// S tile: 128x128, 8x8 microtile (16x16 thread grid).
// PV: 8 rows x 4 dims per thread.
// Softmax runs in base-2 with scale*log2(e) folded into the scores.
// ---------------------------------------------------------------------------
#define BM 128
#define BN 128
#define AD 64
#define PQ 132   // pitch for Qs/Ks: [AD][BM]
#define PVP 68   // pitch for Vs:   [BN][AD]
#define PP 132   // pitch for Ps:   [BM][BN]

#define ATTN_SMEM ((2 * AD * PQ + BN * PVP + BM * PP) * sizeof(float))

__global__ __launch_bounds__(256) void flash_attn2(
    const float* __restrict__ Q, const float* __restrict__ K,
    const float* __restrict__ V, float* __restrict__ O) {
  extern __shared__ float sm[];
  float* Qs = sm;                  // [AD][PQ]  (transposed: Qs[d][row])
  float* Ks = Qs + AD * PQ;        // [AD][PQ]  (transposed: Ks[d][col])
  float* Vs = Ks + AD * PQ;        // [BN][PVP] (natural: Vs[krow][d])
  float* Ps = Vs + BN * PVP;       // [BM][PP]  (natural: Ps[qrow][kcol])

  const int qb = gridDim.x - 1 - blockIdx.x;  // heavy blocks first
  const int h  = blockIdx.y;
  const int tid = threadIdx.x;
  const int ty = tid >> 4;
  const int tx = tid & 15;
  // softmax in base-2: scores_log2 = (q.k) * (1/sqrt(64)) * log2(e)
  const float scale2 = 0.125f * 1.44269504088896f;

  // Load Q block [128 x 64], transposed into Qs[d][row]
  {
    const int r = tid >> 1;
    const int cb = (tid & 1) * 32;
    const float* src = Q + (qb * BM + r) * C_MODEL + h * AD + cb;
#pragma unroll
    for (int i = 0; i < 8; i++) {
      float4 v4 = *(const float4*)(src + i * 4);
      Qs[(cb + i * 4 + 0) * PQ + r] = v4.x;
      Qs[(cb + i * 4 + 1) * PQ + r] = v4.y;
      Qs[(cb + i * 4 + 2) * PQ + r] = v4.z;
      Qs[(cb + i * 4 + 3) * PQ + r] = v4.w;
    }
  }

  float m_i[8], l_i[8], Oacc[8][4];
#pragma unroll
  for (int a = 0; a < 8; a++) {
    m_i[a] = -1e30f; l_i[a] = 0.f;
#pragma unroll
    for (int c = 0; c < 4; c++) Oacc[a][c] = 0.f;
  }

  for (int kt = 0; kt <= qb; kt++) {
    __syncthreads();  // protect Ks/Vs/Ps from previous iteration's readers
    {
      const int r = tid >> 1;
      const int cb = (tid & 1) * 32;
      const float* ks = K + (kt * BN + r) * C_MODEL + h * AD + cb;
      const float* vs = V + (kt * BN + r) * C_MODEL + h * AD + cb;
#pragma unroll
      for (int i = 0; i < 8; i++) {
        float4 kv = *(const float4*)(ks + i * 4);
        Ks[(cb + i * 4 + 0) * PQ + r] = kv.x;
        Ks[(cb + i * 4 + 1) * PQ + r] = kv.y;
        Ks[(cb + i * 4 + 2) * PQ + r] = kv.z;
        Ks[(cb + i * 4 + 3) * PQ + r] = kv.w;
        *(float4*)&Vs[r * PVP + cb + i * 4] = *(const float4*)(vs + i * 4);
      }
    }
    __syncthreads();

    // ---- S = Q K^T (8x8 per thread) ----
    float s[8][8];
#pragma unroll
    for (int a = 0; a < 8; a++)
#pragma unroll
      for (int j = 0; j < 8; j++) s[a][j] = 0.f;
#pragma unroll 4
    for (int k = 0; k < AD; k++) {
      float a[8], b[8];
      *(float4*)&a[0] = *(const float4*)&Qs[k * PQ + ty * 8 + 0];
      *(float4*)&a[4] = *(const float4*)&Qs[k * PQ + ty * 8 + 4];
      *(float4*)&b[0] = *(const float4*)&Ks[k * PQ + tx * 8 + 0];
      *(float4*)&b[4] = *(const float4*)&Ks[k * PQ + tx * 8 + 4];
#pragma unroll
      for (int i = 0; i < 8; i++)
#pragma unroll
        for (int j = 0; j < 8; j++) s[i][j] = fmaf(a[i], b[j], s[i][j]);
    }

    // scale (log2 domain) + causal mask (diagonal tile only)
    if (kt == qb) {
#pragma unroll
      for (int a = 0; a < 8; a++)
#pragma unroll
        for (int j = 0; j < 8; j++)
          s[a][j] = (tx * 8 + j) > (ty * 8 + a) ? -1e30f : s[a][j] * scale2;
    } else {
#pragma unroll
      for (int a = 0; a < 8; a++)
#pragma unroll
        for (int j = 0; j < 8; j++) s[a][j] *= scale2;
    }

    // ---- online softmax (rows spread across 16 tx lanes) ----
#pragma unroll
    for (int a = 0; a < 8; a++) {
      float rm = s[a][0];
#pragma unroll
      for (int j = 1; j < 8; j++) rm = fmaxf(rm, s[a][j]);
#pragma unroll
      for (int off = 8; off > 0; off >>= 1)
        rm = fmaxf(rm, __shfl_xor_sync(0xffffffffu, rm, off));
      const float mnew = fmaxf(m_i[a], rm);
      const float alpha = exp2f(m_i[a] - mnew);
      float rs = 0.f;
#pragma unroll
      for (int j = 0; j < 8; j++) {
        const float p = exp2f(s[a][j] - mnew);
        s[a][j] = p;
        rs += p;
      }
#pragma unroll
      for (int off = 8; off > 0; off >>= 1)
        rs += __shfl_xor_sync(0xffffffffu, rs, off);
      l_i[a] = l_i[a] * alpha + rs;
      m_i[a] = mnew;
#pragma unroll
      for (int c = 0; c < 4; c++) Oacc[a][c] *= alpha;
      // store P row-major (broadcast-friendly reads in PV)
      float4 p0 = make_float4(s[a][0], s[a][1], s[a][2], s[a][3]);
      float4 p1 = make_float4(s[a][4], s[a][5], s[a][6], s[a][7]);
      *(float4*)&Ps[(ty * 8 + a) * PP + tx * 8 + 0] = p0;
      *(float4*)&Ps[(ty * 8 + a) * PP + tx * 8 + 4] = p1;
    }
    __syncthreads();

    // ---- O += P V (8 rows x 4 dims per thread) ----
#pragma unroll 2
    for (int j0 = 0; j0 < BN; j0 += 4) {
      float4 vr[4];
#pragma unroll
      for (int jj = 0; jj < 4; jj++)
        vr[jj] = *(const float4*)&Vs[(j0 + jj) * PVP + tx * 4];
#pragma unroll
      for (int a = 0; a < 8; a++) {
        float4 p4 = *(const float4*)&Ps[(ty * 8 + a) * PP + j0];
        Oacc[a][0] = fmaf(p4.x, vr[0].x, Oacc[a][0]);
        Oacc[a][1] = fmaf(p4.x, vr[0].y, Oacc[a][1]);
        Oacc[a][2] = fmaf(p4.x, vr[0].z, Oacc[a][2]);
        Oacc[a][3] = fmaf(p4.x, vr[0].w, Oacc[a][3]);
        Oacc[a][0] = fmaf(p4.y, vr[1].x, Oacc[a][0]);
        Oacc[a][1] = fmaf(p4.y, vr[1].y, Oacc[a][1]);
        Oacc[a][2] = fmaf(p4.y, vr[1].z, Oacc[a][2]);
        Oacc[a][3] = fmaf(p4.y, vr[1].w, Oacc[a][3]);
        Oacc[a][0] = fmaf(p4.z, vr[2].x, Oacc[a][0]);
        Oacc[a][1] = fmaf(p4.z, vr[2].y, Oacc[a][1]);
        Oacc[a][2] = fmaf(p4.z, vr[2].z, Oacc[a][2]);
        Oacc[a][3] = fmaf(p4.z, vr[2].w, Oacc[a][3]);
        Oacc[a][0] = fmaf(p4.w, vr[3].x, Oacc[a][0]);
        Oacc[a][1] = fmaf(p4.w, vr[3].y, Oacc[a][1]);
        Oacc[a][2] = fmaf(p4.w, vr[3].z, Oacc[a][2]);
        Oacc[a][3] = fmaf(p4.w, vr[3].w, Oacc[a][3]);
      }
    }
  }

  // Epilogue: normalize and store [T, C] head-interleaved
#pragma unroll
  for (int a = 0; a < 8; a++) {
    const float inv = 1.f / l_i[a];
    const int r = qb * BM + ty * 8 + a;
    float4 o;
    o.x = Oacc[a][0] * inv;
    o.y = Oacc[a][1] * inv;
    o.z = Oacc[a][2] * inv;
    o.w = Oacc[a][3] * inv;
    *(float4*)(O + r * C_MODEL + h * AD + tx * 4) = o;
  }
}

// ---------------------------------------------------------------------------
extern "C" void kernel_launch(void* const* d_in, const int* in_sizes, int n_in,
                              void* d_out, int out_size) {
  const float* x  = (const float*)d_in[0];
  const float* Wq = (const float*)d_in[1];
  const float* bq = (const float*)d_in[2];
  const float* Wk = (const float*)d_in[3];
  const float* bk = (const float*)d_in[4];
  const float* Wv = (const float*)d_in[5];
  const float* bv = (const float*)d_in[6];
  const float* Wo = (const float*)d_in[7];
  const float* bo = (const float*)d_in[8];
  float* out = (float*)d_out;

  float *qp, *kp, *vp, *ap;
  cudaGetSymbolAddress((void**)&qp, g_q);
  cudaGetSymbolAddress((void**)&kp, g_k);
  cudaGetSymbolAddress((void**)&vp, g_v);
  cudaGetSymbolAddress((void**)&ap, g_attn);

  cudaFuncSetAttribute(flash_attn2, cudaFuncAttributeMaxDynamicSharedMemorySize,
                       (int)ATTN_SMEM);

  dim3 gb(C_MODEL / 128, T_SEQ / 128);  // (8, 32)
  gemm_bias<<<gb, 256>>>(x, Wq, bq, qp, T_SEQ, C_MODEL, C_MODEL);
  gemm_bias<<<gb, 256>>>(x, Wk, bk, kp, T_SEQ, C_MODEL, C_MODEL);
  gemm_bias<<<gb, 256>>>(x, Wv, bv, vp, T_SEQ, C_MODEL, C_MODEL);

  dim3 ga(T_SEQ / BM, NHEADS);          // (32, 16)
  flash_attn2<<<ga, 256, ATTN_SMEM>>>(qp, kp, vp, ap);

  gemm_bias<<<gb, 256>>>(ap, Wo, bo, out, T_SEQ, C_MODEL, C_MODEL);
}

// round 5
// speedup vs baseline: 1.3672x; 1.3672x over previous
#include <cuda_runtime.h>
#include <math.h>
#include <stdint.h>

#define T_SEQ 4096
#define C_MODEL 1024
#define NHEADS 16
#define DHEAD 64

// Scratch (allocation-free rule: __device__ globals)
__device__ float g_q[T_SEQ * C_MODEL];
__device__ float g_k[T_SEQ * C_MODEL];
__device__ float g_v[T_SEQ * C_MODEL];
__device__ float g_attn[T_SEQ * C_MODEL];

__device__ __forceinline__ uint32_t f2tf32(float x) {
  uint32_t r;
  asm("cvt.rna.tf32.f32 %0, %1;" : "=r"(r) : "f"(x));
  return r;
}

__device__ __forceinline__ void mma_tf32(float* d, const uint32_t* a,
                                         const uint32_t* b) {
  asm volatile(
      "mma.sync.aligned.m16n8k8.row.col.f32.tf32.tf32.f32 "
      "{%0,%1,%2,%3}, {%4,%5,%6,%7}, {%8,%9}, {%0,%1,%2,%3};\n"
      : "+f"(d[0]), "+f"(d[1]), "+f"(d[2]), "+f"(d[3])
      : "r"(a[0]), "r"(a[1]), "r"(a[2]), "r"(a[3]), "r"(b[0]), "r"(b[1]));
}

// ---------------------------------------------------------------------------
// C[M,N] = A[M,K] @ B[N,K]^T + bias[N]   (tf32 tensor cores)
// CTA tile 128x128, BK=32, 256 threads = 8 warps in 2(m) x 4(n).
// Warp tile 64x32 -> 4x4 grid of m16n8k8 mma.
// Smem pitch 36 floats: fragment LDS pattern is bank = lane (conflict-free),
// and float4 staging stores are conflict-free as well.
// ---------------------------------------------------------------------------
#define TPITCH 36

__global__ __launch_bounds__(256) void gemm_bias_tc(
    const float* __restrict__ A, const float* __restrict__ B,
    const float* __restrict__ bias, float* __restrict__ Cout,
    int M, int N, int K) {
  __shared__ uint32_t As[128][TPITCH];
  __shared__ uint32_t Bs[128][TPITCH];

  const int tid = threadIdx.x;
  const int lane = tid & 31;
  const int wid = tid >> 5;
  const int wm = wid >> 2;          // 0..1
  const int wn = wid & 3;           // 0..3
  const int l4 = lane >> 2;         // 0..7
  const int lm4 = lane & 3;         // 0..3
  const int bm = blockIdx.y * 128;
  const int bn = blockIdx.x * 128;

  const int srow = tid >> 1;            // 0..127
  const int scol = (tid & 1) * 16;      // 0 or 16

  float acc[4][4][4];
#pragma unroll
  for (int i = 0; i < 4; i++)
#pragma unroll
    for (int j = 0; j < 4; j++)
#pragma unroll
      for (int c = 0; c < 4; c++) acc[i][j][c] = 0.f;

  const float* Aptr = A + (bm + srow) * K + scol;
  const float* Bptr = B + (bn + srow) * K + scol;

  // prefetch first tile
  float4 pa[4], pb[4];
#pragma unroll
  for (int i = 0; i < 4; i++) {
    pa[i] = *(const float4*)(Aptr + i * 4);
    pb[i] = *(const float4*)(Bptr + i * 4);
  }

  for (int k0 = 0; k0 < K; k0 += 32) {
    __syncthreads();
#pragma unroll
    for (int i = 0; i < 4; i++) {
      uint32_t* ad = &As[srow][scol + i * 4];
      ad[0] = f2tf32(pa[i].x); ad[1] = f2tf32(pa[i].y);
      ad[2] = f2tf32(pa[i].z); ad[3] = f2tf32(pa[i].w);
      uint32_t* bd = &Bs[srow][scol + i * 4];
      bd[0] = f2tf32(pb[i].x); bd[1] = f2tf32(pb[i].y);
      bd[2] = f2tf32(pb[i].z); bd[3] = f2tf32(pb[i].w);
    }
    __syncthreads();

    if (k0 + 32 < K) {  // prefetch next tile (overlaps with mma below)
#pragma unroll
      for (int i = 0; i < 4; i++) {
        pa[i] = *(const float4*)(Aptr + k0 + 32 + i * 4);
        pb[i] = *(const float4*)(Bptr + k0 + 32 + i * 4);
      }
    }

#pragma unroll
    for (int kk = 0; kk < 4; kk++) {
      uint32_t af[4][4], bf[4][2];
#pragma unroll
      for (int i = 0; i < 4; i++) {
        const int r = wm * 64 + i * 16 + l4;
        af[i][0] = As[r][kk * 8 + lm4];
        af[i][1] = As[r + 8][kk * 8 + lm4];
        af[i][2] = As[r][kk * 8 + lm4 + 4];
        af[i][3] = As[r + 8][kk * 8 + lm4 + 4];
      }
#pragma unroll
      for (int j = 0; j < 4; j++) {
        const int n = wn * 32 + j * 8 + l4;
        bf[j][0] = Bs[n][kk * 8 + lm4];
        bf[j][1] = Bs[n][kk * 8 + lm4 + 4];
      }
#pragma unroll
      for (int i = 0; i < 4; i++)
#pragma unroll
        for (int j = 0; j < 4; j++) mma_tf32(acc[i][j], af[i], bf[j]);
    }
  }

  // Epilogue: D rows bm + wm*64 + i*16 + l4 (+8); cols bn + wn*32 + j*8 + lm4*2 (+1)
#pragma unroll
  for (int j = 0; j < 4; j++) {
    const int c = bn + wn * 32 + j * 8 + lm4 * 2;
    const float bi0 = bias[c], bi1 = bias[c + 1];
#pragma unroll
    for (int i = 0; i < 4; i++) {
      const int r = bm + wm * 64 + i * 16 + l4;
      float2 o0 = make_float2(acc[i][j][0] + bi0, acc[i][j][1] + bi1);
      float2 o1 = make_float2(acc[i][j][2] + bi0, acc[i][j][3] + bi1);
      *(float2*)(Cout + r * N + c) = o0;
      *(float2*)(Cout + (r + 8) * N + c) = o1;
    }
  }
}

// ---------------------------------------------------------------------------
// Causal flash attention, fp32, gemm-style tiling (unchanged from R4 pass).
// ---------------------------------------------------------------------------
#define BM 128
#define BN 128
#define AD 64
#define PQ 132
#define PVP 68
#define PP 132

#define ATTN_SMEM ((2 * AD * PQ + BN * PVP + BM * PP) * sizeof(float))

__global__ __launch_bounds__(256) void flash_attn2(
    const float* __restrict__ Q, const float* __restrict__ K,
    const float* __restrict__ V, float* __restrict__ O) {
  extern __shared__ float sm[];
  float* Qs = sm;
  float* Ks = Qs + AD * PQ;
  float* Vs = Ks + AD * PQ;
  float* Ps = Vs + BN * PVP;

  const int qb = gridDim.x - 1 - blockIdx.x;
  const int h  = blockIdx.y;
  const int tid = threadIdx.x;
  const int ty = tid >> 4;
  const int tx = tid & 15;
  const float scale2 = 0.125f * 1.44269504088896f;

  {
    const int r = tid >> 1;
    const int cb = (tid & 1) * 32;
    const float* src = Q + (qb * BM + r) * C_MODEL + h * AD + cb;
#pragma unroll
    for (int i = 0; i < 8; i++) {
      float4 v4 = *(const float4*)(src + i * 4);
      Qs[(cb + i * 4 + 0) * PQ + r] = v4.x;
      Qs[(cb + i * 4 + 1) * PQ + r] = v4.y;
      Qs[(cb + i * 4 + 2) * PQ + r] = v4.z;
      Qs[(cb + i * 4 + 3) * PQ + r] = v4.w;
    }
  }

  float m_i[8], l_i[8], Oacc[8][4];
#pragma unroll
  for (int a = 0; a < 8; a++) {
    m_i[a] = -1e30f; l_i[a] = 0.f;
#pragma unroll
    for (int c = 0; c < 4; c++) Oacc[a][c] = 0.f;
  }

  for (int kt = 0; kt <= qb; kt++) {
    __syncthreads();
    {
      const int r = tid >> 1;
      const int cb = (tid & 1) * 32;
      const float* ks = K + (kt * BN + r) * C_MODEL + h * AD + cb;
      const float* vs = V + (kt * BN + r) * C_MODEL + h * AD + cb;
#pragma unroll
      for (int i = 0; i < 8; i++) {
        float4 kv = *(const float4*)(ks + i * 4);
        Ks[(cb + i * 4 + 0) * PQ + r] = kv.x;
        Ks[(cb + i * 4 + 1) * PQ + r] = kv.y;
        Ks[(cb + i * 4 + 2) * PQ + r] = kv.z;
        Ks[(cb + i * 4 + 3) * PQ + r] = kv.w;
        *(float4*)&Vs[r * PVP + cb + i * 4] = *(const float4*)(vs + i * 4);
      }
    }
    __syncthreads();

    float s[8][8];
#pragma unroll
    for (int a = 0; a < 8; a++)
#pragma unroll
      for (int j = 0; j < 8; j++) s[a][j] = 0.f;
#pragma unroll 4
    for (int k = 0; k < AD; k++) {
      float a[8], b[8];
      *(float4*)&a[0] = *(const float4*)&Qs[k * PQ + ty * 8 + 0];
      *(float4*)&a[4] = *(const float4*)&Qs[k * PQ + ty * 8 + 4];
      *(float4*)&b[0] = *(const float4*)&Ks[k * PQ + tx * 8 + 0];
      *(float4*)&b[4] = *(const float4*)&Ks[k * PQ + tx * 8 + 4];
#pragma unroll
      for (int i = 0; i < 8; i++)
#pragma unroll
        for (int j = 0; j < 8; j++) s[i][j] = fmaf(a[i], b[j], s[i][j]);
    }

    if (kt == qb) {
#pragma unroll
      for (int a = 0; a < 8; a++)
#pragma unroll
        for (int j = 0; j < 8; j++)
          s[a][j] = (tx * 8 + j) > (ty * 8 + a) ? -1e30f : s[a][j] * scale2;
    } else {
#pragma unroll
      for (int a = 0; a < 8; a++)
#pragma unroll
        for (int j = 0; j < 8; j++) s[a][j] *= scale2;
    }

#pragma unroll
    for (int a = 0; a < 8; a++) {
      float rm = s[a][0];
#pragma unroll
      for (int j = 1; j < 8; j++) rm = fmaxf(rm, s[a][j]);
#pragma unroll
      for (int off = 8; off > 0; off >>= 1)
        rm = fmaxf(rm, __shfl_xor_sync(0xffffffffu, rm, off));
      const float mnew = fmaxf(m_i[a], rm);
      const float alpha = exp2f(m_i[a] - mnew);
      float rs = 0.f;
#pragma unroll
      for (int j = 0; j < 8; j++) {
        const float p = exp2f(s[a][j] - mnew);
        s[a][j] = p;
        rs += p;
      }
#pragma unroll
      for (int off = 8; off > 0; off >>= 1)
        rs += __shfl_xor_sync(0xffffffffu, rs, off);
      l_i[a] = l_i[a] * alpha + rs;
      m_i[a] = mnew;
#pragma unroll
      for (int c = 0; c < 4; c++) Oacc[a][c] *= alpha;
      float4 p0 = make_float4(s[a][0], s[a][1], s[a][2], s[a][3]);
      float4 p1 = make_float4(s[a][4], s[a][5], s[a][6], s[a][7]);
      *(float4*)&Ps[(ty * 8 + a) * PP + tx * 8 + 0] = p0;
      *(float4*)&Ps[(ty * 8 + a) * PP + tx * 8 + 4] = p1;
    }
    __syncthreads();

#pragma unroll 2
    for (int j0 = 0; j0 < BN; j0 += 4) {
      float4 vr[4];
#pragma unroll
      for (int jj = 0; jj < 4; jj++)
        vr[jj] = *(const float4*)&Vs[(j0 + jj) * PVP + tx * 4];
#pragma unroll
      for (int a = 0; a < 8; a++) {
        float4 p4 = *(const float4*)&Ps[(ty * 8 + a) * PP + j0];
        Oacc[a][0] = fmaf(p4.x, vr[0].x, Oacc[a][0]);
        Oacc[a][1] = fmaf(p4.x, vr[0].y, Oacc[a][1]);
        Oacc[a][2] = fmaf(p4.x, vr[0].z, Oacc[a][2]);
        Oacc[a][3] = fmaf(p4.x, vr[0].w, Oacc[a][3]);
        Oacc[a][0] = fmaf(p4.y, vr[1].x, Oacc[a][0]);
        Oacc[a][1] = fmaf(p4.y, vr[1].y, Oacc[a][1]);
        Oacc[a][2] = fmaf(p4.y, vr[1].z, Oacc[a][2]);
        Oacc[a][3] = fmaf(p4.y, vr[1].w, Oacc[a][3]);
        Oacc[a][0] = fmaf(p4.z, vr[2].x, Oacc[a][0]);
        Oacc[a][1] = fmaf(p4.z, vr[2].y, Oacc[a][1]);
        Oacc[a][2] = fmaf(p4.z, vr[2].z, Oacc[a][2]);
        Oacc[a][3] = fmaf(p4.z, vr[2].w, Oacc[a][3]);
        Oacc[a][0] = fmaf(p4.w, vr[3].x, Oacc[a][0]);
        Oacc[a][1] = fmaf(p4.w, vr[3].y, Oacc[a][1]);
        Oacc[a][2] = fmaf(p4.w, vr[3].z, Oacc[a][2]);
        Oacc[a][3] = fmaf(p4.w, vr[3].w, Oacc[a][3]);
      }
    }
  }

#pragma unroll
  for (int a = 0; a < 8; a++) {
    const float inv = 1.f / l_i[a];
    const int r = qb * BM + ty * 8 + a;
    float4 o;
    o.x = Oacc[a][0] * inv;
    o.y = Oacc[a][1] * inv;
    o.z = Oacc[a][2] * inv;
    o.w = Oacc[a][3] * inv;
    *(float4*)(O + r * C_MODEL + h * AD + tx * 4) = o;
  }
}

// ---------------------------------------------------------------------------
extern "C" void kernel_launch(void* const* d_in, const int* in_sizes, int n_in,
                              void* d_out, int out_size) {
  const float* x  = (const float*)d_in[0];
  const float* Wq = (const float*)d_in[1];
  const float* bq = (const float*)d_in[2];
  const float* Wk = (const float*)d_in[3];
  const float* bk = (const float*)d_in[4];
  const float* Wv = (const float*)d_in[5];
  const float* bv = (const float*)d_in[6];
  const float* Wo = (const float*)d_in[7];
  const float* bo = (const float*)d_in[8];
  float* out = (float*)d_out;

  float *qp, *kp, *vp, *ap;
  cudaGetSymbolAddress((void**)&qp, g_q);
  cudaGetSymbolAddress((void**)&kp, g_k);
  cudaGetSymbolAddress((void**)&vp, g_v);
  cudaGetSymbolAddress((void**)&ap, g_attn);

  cudaFuncSetAttribute(flash_attn2, cudaFuncAttributeMaxDynamicSharedMemorySize,
                       (int)ATTN_SMEM);

  dim3 gb(C_MODEL / 128, T_SEQ / 128);  // (8, 32)
  gemm_bias_tc<<<gb, 256>>>(x, Wq, bq, qp, T_SEQ, C_MODEL, C_MODEL);
  gemm_bias_tc<<<gb, 256>>>(x, Wk, bk, kp, T_SEQ, C_MODEL, C_MODEL);
  gemm_bias_tc<<<gb, 256>>>(x, Wv, bv, vp, T_SEQ, C_MODEL, C_MODEL);

  dim3 ga(T_SEQ / BM, NHEADS);          // (32, 16)
  flash_attn2<<<ga, 256, ATTN_SMEM>>>(qp, kp, vp, ap);

  gemm_bias_tc<<<gb, 256>>>(ap, Wo, bo, out, T_SEQ, C_MODEL, C_MODEL);
}